// round 7
// baseline (speedup 1.0000x reference)
#include <cuda_runtime.h>
#include <cuda_bf16.h>
#include <math.h>

// DWT1D Haar analysis via banded-matrix exploit (2 taps/row, periodic).
// out[b,k,c]   = h00*x[b,2k,c] + h01*x[b,2k+1,c]   (same linear offset as x[b,2k,c])
// out[b,k,C+c] = h10*x[b,2k,c] + h11*x[b,2k+1,c]   (same linear offset as x[b,2k+1,c])
//
// Round-7: pin BOTH streams in L2 with evict_last (x + out = 67MB < 126MB L2).
// R5 hinted only loads; steady-state DRAM traffic is dominated by writebacks
// of out's dirty lines, so stores must be evict_last too. Target steady state:
// reads = L2 hits, stores = dirty-line write hits, DRAM idle.

__device__ __forceinline__ float4 ldg_el(const float4* p, unsigned long long pol) {
    float4 v;
    asm volatile("ld.global.nc.L2::cache_hint.v4.f32 {%0,%1,%2,%3}, [%4], %5;"
                 : "=f"(v.x), "=f"(v.y), "=f"(v.z), "=f"(v.w)
                 : "l"(p), "l"(pol));
    return v;
}

__device__ __forceinline__ void stg_el(float4* p, float4 v, unsigned long long pol) {
    asm volatile("st.global.L2::cache_hint.v4.f32 [%0], {%1,%2,%3,%4}, %5;"
                 :: "l"(p), "f"(v.x), "f"(v.y), "f"(v.z), "f"(v.w), "l"(pol)
                 : "memory");
}

__global__ void __launch_bounds__(256) dwt1d_haar_r7(
    const float4* __restrict__ x,
    const float*  __restrict__ A,
    float4*       __restrict__ out,
    int n_threads,            // total float4-pair slots = total_floats/8
    size_t half_row_off)      // (N/2)*N
{
    int idx = blockIdx.x * blockDim.x + threadIdx.x;
    if (idx >= n_threads) return;

    const float h00 = __ldg(&A[0]);
    const float h01 = __ldg(&A[1]);
    const float h10 = __ldg(&A[half_row_off]);
    const float h11 = __ldg(&A[half_row_off + 1]);

    unsigned long long pol;
    asm volatile("createpolicy.fractional.L2::evict_last.b64 %0, 1.0;" : "=l"(pol));

    // slot -> (pair, c): even-row float4 at pair*32 + c, odd-row at +16.
    const int pair = idx >> 4;
    const int c    = idx & 15;
    const size_t base = (size_t)pair * 32 + c;

    const float4 a = ldg_el(&x[base],      pol);  // x[b, 2k,   4c:4c+4]
    const float4 b = ldg_el(&x[base + 16], pol);  // x[b, 2k+1, 4c:4c+4]

    float4 lo, hi;
    lo.x = a.x * h00 + b.x * h01;
    lo.y = a.y * h00 + b.y * h01;
    lo.z = a.z * h00 + b.z * h01;
    lo.w = a.w * h00 + b.w * h01;

    hi.x = a.x * h10 + b.x * h11;
    hi.y = a.y * h10 + b.y * h11;
    hi.z = a.z * h10 + b.z * h11;
    hi.w = a.w * h10 + b.w * h11;

    stg_el(&out[base],      lo, pol);   // lowpass  band
    stg_el(&out[base + 16], hi, pol);   // highpass band
}

extern "C" void kernel_launch(void* const* d_in, const int* in_sizes, int n_in,
                              void* d_out, int out_size)
{
    const float* x = (const float*)d_in[0];   // [B, N, C] f32
    const float* A = (const float*)d_in[1];   // [N, N]    f32
    float* out = (float*)d_out;               // [B, N/2, 2C] f32

    long long a_elems = (long long)in_sizes[1];
    int N = (int)llround(sqrt((double)a_elems));
    size_t half_row_off = (size_t)(N / 2) * (size_t)N;

    long long total = (long long)in_sizes[0];
    int n_threads = (int)(total / 8);         // 8 floats per thread

    const int TPB = 256;
    int blocks = (n_threads + TPB - 1) / TPB;

    dwt1d_haar_r7<<<blocks, TPB>>>(
        (const float4*)x, A, (float4*)out, n_threads, half_row_off);
}

// round 8
// speedup vs baseline: 1.0269x; 1.0269x over previous
#include <cuda_runtime.h>
#include <cuda_bf16.h>
#include <math.h>

// DWT1D Haar analysis via banded-matrix exploit (2 taps/row, periodic).
// out[b,k,c]   = h00*x[b,2k,c] + h01*x[b,2k+1,c]   (same linear offset as x[b,2k,c])
// out[b,k,C+c] = h10*x[b,2k,c] + h11*x[b,2k+1,c]   (same linear offset as x[b,2k+1,c])
//
// Round-8: exact R1 shape (best measured: 10.72us) + ONE change: __stcs
// streaming stores, so the zero-reuse write stream is marked evict-first and
// doesn't displace in-flight read sectors in L2. Op is at the mixed
// read/write HBM roofline (67MB / ~6.2TB/s); this is the last overhead trim.

__global__ void __launch_bounds__(256) dwt1d_haar_r8(
    const float4* __restrict__ x,
    const float*  __restrict__ A,
    float4*       __restrict__ out,
    int n_threads,            // total float4-pair slots = total_floats/8
    size_t half_row_off)      // (N/2)*N
{
    int idx = blockIdx.x * blockDim.x + threadIdx.x;
    if (idx >= n_threads) return;

    const float h00 = __ldg(&A[0]);
    const float h01 = __ldg(&A[1]);
    const float h10 = __ldg(&A[half_row_off]);
    const float h11 = __ldg(&A[half_row_off + 1]);

    // slot -> (pair, c): even-row float4 at pair*32 + c, odd-row at +16.
    const int pair = idx >> 4;
    const int c    = idx & 15;
    const size_t base = (size_t)pair * 32 + c;

    const float4 a = x[base];        // x[b, 2k,   4c:4c+4]
    const float4 b = x[base + 16];   // x[b, 2k+1, 4c:4c+4]

    float4 lo, hi;
    lo.x = a.x * h00 + b.x * h01;
    lo.y = a.y * h00 + b.y * h01;
    lo.z = a.z * h00 + b.z * h01;
    lo.w = a.w * h00 + b.w * h01;

    hi.x = a.x * h10 + b.x * h11;
    hi.y = a.y * h10 + b.y * h11;
    hi.z = a.z * h10 + b.z * h11;
    hi.w = a.w * h10 + b.w * h11;

    __stcs(&out[base],      lo);   // lowpass  band (streaming, evict-first)
    __stcs(&out[base + 16], hi);   // highpass band
}

extern "C" void kernel_launch(void* const* d_in, const int* in_sizes, int n_in,
                              void* d_out, int out_size)
{
    const float* x = (const float*)d_in[0];   // [B, N, C] f32
    const float* A = (const float*)d_in[1];   // [N, N]    f32
    float* out = (float*)d_out;               // [B, N/2, 2C] f32

    long long a_elems = (long long)in_sizes[1];
    int N = (int)llround(sqrt((double)a_elems));
    size_t half_row_off = (size_t)(N / 2) * (size_t)N;

    long long total = (long long)in_sizes[0];
    int n_threads = (int)(total / 8);         // 8 floats per thread

    const int TPB = 256;
    int blocks = (n_threads + TPB - 1) / TPB;

    dwt1d_haar_r8<<<blocks, TPB>>>(
        (const float4*)x, A, (float4*)out, n_threads, half_row_off);
}

// round 9
// speedup vs baseline: 1.0299x; 1.0030x over previous
#include <cuda_runtime.h>
#include <cuda_bf16.h>
#include <math.h>

// DWT1D Haar analysis via banded-matrix exploit (2 taps/row, periodic).
// out[b,k,c]   = h00*x[b,2k,c] + h01*x[b,2k+1,c]   (same linear offset as x[b,2k,c])
// out[b,k,C+c] = h10*x[b,2k,c] + h11*x[b,2k+1,c]   (same linear offset as x[b,2k+1,c])
//
// Round-9 (final): champion R1/R8 shape with BOTH streams marked streaming
// (__ldcs reads, __stcs writes). Zero reuse either direction -> L2 as pure
// streaming buffer, minimal dirty-line churn, DRAM-burst-friendly ordering.
// Kernel is at the mixed read/write HBM roofline (67MB @ ~6.26TB/s = 78% of
// 8TB/s spec); all structural variants (MLP, occupancy, vector width, wave
// shape, L2 policies) measured neutral across rounds 1-8.

__global__ void __launch_bounds__(256) dwt1d_haar_r9(
    const float4* __restrict__ x,
    const float*  __restrict__ A,
    float4*       __restrict__ out,
    int n_threads,            // total float4-pair slots = total_floats/8
    size_t half_row_off)      // (N/2)*N
{
    int idx = blockIdx.x * blockDim.x + threadIdx.x;
    if (idx >= n_threads) return;

    const float h00 = __ldg(&A[0]);
    const float h01 = __ldg(&A[1]);
    const float h10 = __ldg(&A[half_row_off]);
    const float h11 = __ldg(&A[half_row_off + 1]);

    // slot -> (pair, c): even-row float4 at pair*32 + c, odd-row at +16.
    const int pair = idx >> 4;
    const int c    = idx & 15;
    const size_t base = (size_t)pair * 32 + c;

    const float4 a = __ldcs(&x[base]);        // x[b, 2k,   4c:4c+4] (streaming)
    const float4 b = __ldcs(&x[base + 16]);   // x[b, 2k+1, 4c:4c+4] (streaming)

    float4 lo, hi;
    lo.x = a.x * h00 + b.x * h01;
    lo.y = a.y * h00 + b.y * h01;
    lo.z = a.z * h00 + b.z * h01;
    lo.w = a.w * h00 + b.w * h01;

    hi.x = a.x * h10 + b.x * h11;
    hi.y = a.y * h10 + b.y * h11;
    hi.z = a.z * h10 + b.z * h11;
    hi.w = a.w * h10 + b.w * h11;

    __stcs(&out[base],      lo);   // lowpass  band (streaming store)
    __stcs(&out[base + 16], hi);   // highpass band (streaming store)
}

extern "C" void kernel_launch(void* const* d_in, const int* in_sizes, int n_in,
                              void* d_out, int out_size)
{
    const float* x = (const float*)d_in[0];   // [B, N, C] f32
    const float* A = (const float*)d_in[1];   // [N, N]    f32
    float* out = (float*)d_out;               // [B, N/2, 2C] f32

    long long a_elems = (long long)in_sizes[1];
    int N = (int)llround(sqrt((double)a_elems));
    size_t half_row_off = (size_t)(N / 2) * (size_t)N;

    long long total = (long long)in_sizes[0];
    int n_threads = (int)(total / 8);         // 8 floats per thread

    const int TPB = 256;
    int blocks = (n_threads + TPB - 1) / TPB;

    dwt1d_haar_r9<<<blocks, TPB>>>(
        (const float4*)x, A, (float4*)out, n_threads, half_row_off);
}